// round 7
// baseline (speedup 1.0000x reference)
#include <cuda_runtime.h>
#include <cuda_bf16.h>
#include <cuda_fp16.h>
#include <cstdint>

// Problem constants (match reference setup_inputs)
#define NNODES 50000
#define NEDGES 640000
// IN_DIM = 128, HID = 128, OUT = 64

// ---------------------------------------------------------------------------
// Device scratch (allocation-free rule: __device__ globals)
// ---------------------------------------------------------------------------
__device__ float  g_C1s[NNODES * 128];    // layer1 self projection (fp32)
__device__ __half g_P1[NNODES * 128];     // layer1 neighbor projection (fp16)
__device__ float4 g_H1[NNODES * 32];      // hidden activations [N,128]
__device__ float  g_C2s[NNODES * 64];     // layer2 self projection (fp32)
__device__ __half g_P2[NNODES * 64];      // layer2 neighbor projection (fp16)
// CSR build scratch
__device__ int    g_cnt[NNODES];
__device__ int    g_off[NNODES];
__device__ int    g_cur[NNODES];
__device__ int    g_csr[NEDGES];
__device__ int    g_blkSums[128];

// ---------------------------------------------------------------------------
// Helpers
// ---------------------------------------------------------------------------
__device__ __forceinline__ uint32_t smem_u32(const void* p) {
    uint32_t a;
    asm("{ .reg .u64 t; cvta.to.shared.u64 t, %1; cvt.u32.u64 %0, t; }"
        : "=r"(a) : "l"(p));
    return a;
}
__device__ __forceinline__ void ldsm4(uint32_t* r, uint32_t addr) {
    asm volatile("ldmatrix.sync.aligned.m8n8.x4.shared.b16 {%0,%1,%2,%3}, [%4];"
                 : "=r"(r[0]), "=r"(r[1]), "=r"(r[2]), "=r"(r[3]) : "r"(addr));
}
__device__ __forceinline__ void mma_bf16(float* d, const uint32_t* a,
                                         uint32_t b0, uint32_t b1) {
    asm volatile(
        "mma.sync.aligned.m16n8k16.row.col.f32.bf16.bf16.f32 "
        "{%0,%1,%2,%3}, {%4,%5,%6,%7}, {%8,%9}, {%0,%1,%2,%3};"
        : "+f"(d[0]), "+f"(d[1]), "+f"(d[2]), "+f"(d[3])
        : "r"(a[0]), "r"(a[1]), "r"(a[2]), "r"(a[3]), "r"(b0), "r"(b1));
}
// Accumulate 8 fp16 values (uint4) into 8 fp32 accumulators
__device__ __forceinline__ void accum8(float* a, uint4 v) {
    __half2 h0 = *reinterpret_cast<__half2*>(&v.x);
    __half2 h1 = *reinterpret_cast<__half2*>(&v.y);
    __half2 h2 = *reinterpret_cast<__half2*>(&v.z);
    __half2 h3 = *reinterpret_cast<__half2*>(&v.w);
    float2 f0 = __half22float2(h0);
    float2 f1 = __half22float2(h1);
    float2 f2 = __half22float2(h2);
    float2 f3 = __half22float2(h3);
    a[0] += f0.x; a[1] += f0.y; a[2] += f1.x; a[3] += f1.y;
    a[4] += f2.x; a[5] += f2.y; a[6] += f3.x; a[7] += f3.y;
}

// ---------------------------------------------------------------------------
// CSR build: zero counts -> histogram -> scanA -> scanC(+parallel prefix) -> scatter
// ---------------------------------------------------------------------------
__global__ void zero_cnt_kernel() {
    int i = blockIdx.x * blockDim.x + threadIdx.x;
    if (i < NNODES) g_cnt[i] = 0;
}
__global__ void hist_kernel(const int* __restrict__ dst) {
    int e = blockIdx.x * blockDim.x + threadIdx.x;
    if (e < NEDGES) atomicAdd(&g_cnt[dst[e]], 1);
}
__global__ void scanA_kernel() {
    __shared__ int s[512];
    int b = blockIdx.x, t = threadIdx.x;
    int i = b * 512 + t;
    int v = (i < NNODES) ? g_cnt[i] : 0;
    s[t] = v;
    __syncthreads();
#pragma unroll
    for (int d = 1; d < 512; d <<= 1) {
        int x = (t >= d) ? s[t - d] : 0;
        __syncthreads();
        s[t] += x;
        __syncthreads();
    }
    if (i < NNODES) g_off[i] = s[t] - v;
    if (t == 511) g_blkSums[b] = s[t];
}
__global__ void scanC_kernel(int nblocks) {
    __shared__ int s[128];
    int t = threadIdx.x;
    if (t < 128) s[t] = (t < nblocks) ? g_blkSums[t] : 0;
    __syncthreads();
#pragma unroll
    for (int d = 1; d < 128; d <<= 1) {
        int x = 0;
        if (t < 128 && t >= d) x = s[t - d];
        __syncthreads();
        if (t < 128) s[t] += x;
        __syncthreads();
    }
    int i = blockIdx.x * blockDim.x + t;
    if (i < NNODES) {
        int blk = i >> 9;
        int pre = (blk == 0) ? 0 : s[blk - 1];
        int o = g_off[i] + pre;
        g_off[i] = o;
        g_cur[i] = o;
    }
}
__global__ void scatter_kernel(const int* __restrict__ src,
                               const int* __restrict__ dst) {
    int e = blockIdx.x * blockDim.x + threadIdx.x;
    if (e < NEDGES) {
        int d = dst[e];
        int p = atomicAdd(&g_cur[d], 1);
        g_csr[p] = src[e];
    }
}

// ---------------------------------------------------------------------------
// Tensor-core GEMM via mma.sync (HMMA), split-bf16 (3 terms, fp32 accum).
// Weights are split fp32 -> bf16 hi/lo IN-KERNEL (no prep pass):
//   concat row t = h*128+n: t < NSELF -> W0[t], else W1[t-NSELF]   ([n][k] fp32)
// Cols [0, NSELF) -> fp32 Cself; cols [NSELF, NOUT) -> fp16 Pneigh.
// CTA = 256 threads (8 warps). Warp tile = 32 rows x 64 cols.
// SMEM: AH[128][136] AL[128][136] WH[128][136] WL[128][136] bf16 (139 KB)
// ---------------------------------------------------------------------------
template <int NOUT, int NSELF>
__global__ void __launch_bounds__(256)
gemm_mma_kernel(const float* __restrict__ A,
                const float* __restrict__ W0,
                const float* __restrict__ W1,
                float* __restrict__ Cself,
                __half* __restrict__ Pneigh, int M) {
    constexpr int ASTR = 136;
    constexpr int WSTR = 136;
    constexpr int NP = NOUT - NSELF;
    extern __shared__ __nv_bfloat16 smem[];
    __nv_bfloat16* sAH = smem;                    // 128*136
    __nv_bfloat16* sAL = sAH + 128 * ASTR;
    __nv_bfloat16* sWH = sAL + 128 * ASTR;        // 128*136
    __nv_bfloat16* sWL = sWH + 128 * WSTR;

    int tid = threadIdx.x;
    int warp = tid >> 5, lane = tid & 31;
    int rg = warp >> 1, cg = warp & 1;
    int base = blockIdx.x * 128;

    // ---- Load A tile (128 rows x 128 fp32), split to bf16 hi/lo in SMEM ----
    {
        int row = tid >> 1;
        int cbase = (tid & 1) * 64;
        int grow = base + row;
        const float4* A4 = reinterpret_cast<const float4*>(A);
#pragma unroll
        for (int i = 0; i < 8; i++) {
            float4 u, v;
            if (grow < M) {
                u = A4[(size_t)grow * 32 + (cbase >> 2) + 2 * i];
                v = A4[(size_t)grow * 32 + (cbase >> 2) + 2 * i + 1];
            } else {
                u = v = make_float4(0.f, 0.f, 0.f, 0.f);
            }
            float f[8] = {u.x, u.y, u.z, u.w, v.x, v.y, v.z, v.w};
            alignas(16) __nv_bfloat16 hb[8], lb[8];
#pragma unroll
            for (int q = 0; q < 8; q++) {
                __nv_bfloat16 h = __float2bfloat16_rn(f[q]);
                hb[q] = h;
                lb[q] = __float2bfloat16_rn(f[q] - __bfloat162float(h));
            }
            int off = row * ASTR + cbase + 8 * i;
            *reinterpret_cast<uint4*>(sAH + off) = *reinterpret_cast<uint4*>(hb);
            *reinterpret_cast<uint4*>(sAL + off) = *reinterpret_cast<uint4*>(lb);
        }
    }

    // Per-thread ldmatrix base offsets
    int g8 = lane >> 3, j8 = lane & 7;
    uint32_t aA0 = smem_u32(sAH) +
                   (uint32_t)(((rg * 32 + (g8 & 1) * 8 + j8) * ASTR + (g8 >> 1) * 8) * 2);
    constexpr uint32_t A_MB = 16u * ASTR * 2u;        // m-block stride
    constexpr uint32_t A_LO = 128u * ASTR * 2u;       // hi->lo plane
    uint32_t aB0 = smem_u32(sWH) +
                   (uint32_t)(((cg * 64 + (g8 >> 1) * 8 + j8) * WSTR + (g8 & 1) * 8) * 2);
    constexpr uint32_t B_NP = 16u * WSTR * 2u;        // nblk-pair stride
    constexpr uint32_t B_LO = 128u * WSTR * 2u;       // hi->lo plane

#pragma unroll
    for (int h = 0; h < NOUT / 128; h++) {
        __syncthreads();
        // ---- Load W strip (128 rows x 128 k fp32), split hi/lo in SMEM ----
        {
            int n = tid >> 1;
            int kq = (tid & 1) * 64;
            int t = h * 128 + n;
            const float* wrow = (t < NSELF)
                ? (W0 + (size_t)t * 128 + kq)
                : (W1 + (size_t)(t - NSELF) * 128 + kq);
            const float4* w4 = reinterpret_cast<const float4*>(wrow);
#pragma unroll
            for (int i = 0; i < 8; i++) {
                float4 u = w4[2 * i];
                float4 v = w4[2 * i + 1];
                float f[8] = {u.x, u.y, u.z, u.w, v.x, v.y, v.z, v.w};
                alignas(16) __nv_bfloat16 hb[8], lb[8];
#pragma unroll
                for (int q = 0; q < 8; q++) {
                    __nv_bfloat16 hh = __float2bfloat16_rn(f[q]);
                    hb[q] = hh;
                    lb[q] = __float2bfloat16_rn(f[q] - __bfloat162float(hh));
                }
                int off = n * WSTR + kq + 8 * i;
                *reinterpret_cast<uint4*>(sWH + off) = *reinterpret_cast<uint4*>(hb);
                *reinterpret_cast<uint4*>(sWL + off) = *reinterpret_cast<uint4*>(lb);
            }
        }
        __syncthreads();

        float acc[64];
#pragma unroll
        for (int i = 0; i < 64; i++) acc[i] = 0.f;

#pragma unroll
        for (int ks = 0; ks < 8; ks++) {
            uint32_t kb = (uint32_t)(ks * 32);
            uint32_t ah0[4], al0[4], ah1[4], al1[4];
            ldsm4(ah0, aA0 + kb);
            ldsm4(al0, aA0 + A_LO + kb);
            ldsm4(ah1, aA0 + A_MB + kb);
            ldsm4(al1, aA0 + A_MB + A_LO + kb);
#pragma unroll
            for (int np = 0; np < 4; np++) {
                uint32_t bh[4], bl[4];
                ldsm4(bh, aB0 + np * B_NP + kb);
                ldsm4(bl, aB0 + B_LO + np * B_NP + kb);
                float* d00 = acc + (0 * 8 + np * 2) * 4;
                float* d01 = acc + (0 * 8 + np * 2 + 1) * 4;
                float* d10 = acc + (1 * 8 + np * 2) * 4;
                float* d11 = acc + (1 * 8 + np * 2 + 1) * 4;
                mma_bf16(d00, ah0, bh[0], bh[1]);
                mma_bf16(d00, ah0, bl[0], bl[1]);
                mma_bf16(d00, al0, bh[0], bh[1]);
                mma_bf16(d01, ah0, bh[2], bh[3]);
                mma_bf16(d01, ah0, bl[2], bl[3]);
                mma_bf16(d01, al0, bh[2], bh[3]);
                mma_bf16(d10, ah1, bh[0], bh[1]);
                mma_bf16(d10, ah1, bl[0], bl[1]);
                mma_bf16(d10, al1, bh[0], bh[1]);
                mma_bf16(d11, ah1, bh[2], bh[3]);
                mma_bf16(d11, ah1, bl[2], bl[3]);
                mma_bf16(d11, al1, bh[2], bh[3]);
            }
        }

        // ---- Flush ----
        int rq = lane >> 2;
        int cq = 2 * (lane & 3);
#pragma unroll
        for (int mb = 0; mb < 2; mb++) {
#pragma unroll
            for (int nb = 0; nb < 8; nb++) {
                float* d = acc + (mb * 8 + nb) * 4;
                int r0 = base + rg * 32 + mb * 16 + rq;
                int col = h * 128 + cg * 64 + nb * 8 + cq;
                if (col < NSELF) {
                    if (r0 < M)
                        *reinterpret_cast<float2*>(&Cself[(size_t)r0 * NSELF + col]) =
                            make_float2(d[0], d[1]);
                    if (r0 + 8 < M)
                        *reinterpret_cast<float2*>(&Cself[(size_t)(r0 + 8) * NSELF + col]) =
                            make_float2(d[2], d[3]);
                } else {
                    int pc = col - NSELF;
                    if (r0 < M)
                        *reinterpret_cast<__half2*>(&Pneigh[(size_t)r0 * NP + pc]) =
                            __floats2half2_rn(d[0], d[1]);
                    if (r0 + 8 < M)
                        *reinterpret_cast<__half2*>(&Pneigh[(size_t)(r0 + 8) * NP + pc]) =
                            __floats2half2_rn(d[2], d[3]);
                }
            }
        }
    }
}

// ---------------------------------------------------------------------------
// Fused CSR aggregation + epilogue, layer 1.
// Warp per node, HALF-WARP per edge: 16 lanes x uint4 (16B) = 256B row.
// Two edges in flight per load round, unroll 4 -> 8 outstanding gathers.
// Final shfl_xor(16) combines halves.
// ---------------------------------------------------------------------------
__global__ void agg_fin1_kernel(const float* __restrict__ b1) {
    int node = (blockIdx.x * blockDim.x + threadIdx.x) >> 5;
    int lane = threadIdx.x & 31;
    if (node >= NNODES) return;
    int half = lane >> 4;
    int sub = lane & 15;

    int beg = g_off[node];
    int cnt = g_cnt[node];
    int end = beg + cnt;

    const uint4* P = reinterpret_cast<const uint4*>(g_P1);  // row stride 16
    float a0[8] = {0, 0, 0, 0, 0, 0, 0, 0};
    float a1[8] = {0, 0, 0, 0, 0, 0, 0, 0};
    float a2[8] = {0, 0, 0, 0, 0, 0, 0, 0};
    float a3[8] = {0, 0, 0, 0, 0, 0, 0, 0};

    int j = beg;
    for (; j + 8 <= end; j += 8) {
        int s0 = g_csr[j + half];
        int s1 = g_csr[j + 2 + half];
        int s2 = g_csr[j + 4 + half];
        int s3 = g_csr[j + 6 + half];
        accum8(a0, P[(size_t)s0 * 16 + sub]);
        accum8(a1, P[(size_t)s1 * 16 + sub]);
        accum8(a2, P[(size_t)s2 * 16 + sub]);
        accum8(a3, P[(size_t)s3 * 16 + sub]);
    }
    for (; j + 2 <= end; j += 2) {
        int s = g_csr[j + half];
        accum8(a0, P[(size_t)s * 16 + sub]);
    }
    if (j < end && half == 0) {
        int s = g_csr[j];
        accum8(a1, P[(size_t)s * 16 + sub]);
    }

    float acc[8];
#pragma unroll
    for (int i = 0; i < 8; i++) {
        acc[i] = (a0[i] + a1[i]) + (a2[i] + a3[i]);
        acc[i] += __shfl_xor_sync(0xffffffffu, acc[i], 16);
    }

    if (half == 0) {
        float rdeg = 1.0f / fmaxf((float)cnt, 1.0f);
        const float4* S = reinterpret_cast<const float4*>(g_C1s);
        const float4* B = reinterpret_cast<const float4*>(b1);
        float4 s0 = S[node * 32 + 2 * sub];
        float4 s1 = S[node * 32 + 2 * sub + 1];
        float4 bb0 = B[2 * sub];
        float4 bb1 = B[2 * sub + 1];
        float4 h0, h1;
        h0.x = fmaxf(fmaf(acc[0], rdeg, s0.x) + bb0.x, 0.f);
        h0.y = fmaxf(fmaf(acc[1], rdeg, s0.y) + bb0.y, 0.f);
        h0.z = fmaxf(fmaf(acc[2], rdeg, s0.z) + bb0.z, 0.f);
        h0.w = fmaxf(fmaf(acc[3], rdeg, s0.w) + bb0.w, 0.f);
        h1.x = fmaxf(fmaf(acc[4], rdeg, s1.x) + bb1.x, 0.f);
        h1.y = fmaxf(fmaf(acc[5], rdeg, s1.y) + bb1.y, 0.f);
        h1.z = fmaxf(fmaf(acc[6], rdeg, s1.z) + bb1.z, 0.f);
        h1.w = fmaxf(fmaf(acc[7], rdeg, s1.w) + bb1.w, 0.f);
        g_H1[node * 32 + 2 * sub] = h0;
        g_H1[node * 32 + 2 * sub + 1] = h1;
    }
}

// ---------------------------------------------------------------------------
// Fused CSR aggregation + epilogue, layer 2.
// Warp per node, QUARTER-WARP per edge: 8 lanes x uint4 = 128B row.
// Four edges in flight per load round. shfl_xor(8) + shfl_xor(16) combine.
// ---------------------------------------------------------------------------
__global__ void agg_fin2_kernel(const float* __restrict__ b2,
                                float4* __restrict__ out) {
    int node = (blockIdx.x * blockDim.x + threadIdx.x) >> 5;
    int lane = threadIdx.x & 31;
    if (node >= NNODES) return;
    int quarter = lane >> 3;
    int sub = lane & 7;

    int beg = g_off[node];
    int cnt = g_cnt[node];
    int end = beg + cnt;

    const uint4* P = reinterpret_cast<const uint4*>(g_P2);  // row stride 8
    float a0[8] = {0, 0, 0, 0, 0, 0, 0, 0};
    float a1[8] = {0, 0, 0, 0, 0, 0, 0, 0};
    float a2[8] = {0, 0, 0, 0, 0, 0, 0, 0};
    float a3[8] = {0, 0, 0, 0, 0, 0, 0, 0};

    int j = beg;
    for (; j + 8 <= end; j += 8) {
        int s0 = g_csr[j + quarter];
        int s1 = g_csr[j + 4 + quarter];
        accum8(a0, P[(size_t)s0 * 8 + sub]);
        accum8(a1, P[(size_t)s1 * 8 + sub]);
    }
    for (; j + 4 <= end; j += 4) {
        int s = g_csr[j + quarter];
        accum8(a2, P[(size_t)s * 8 + sub]);
    }
    if (j < end && quarter < end - j) {
        int s = g_csr[j + quarter];
        accum8(a3, P[(size_t)s * 8 + sub]);
    }

    float acc[8];
#pragma unroll
    for (int i = 0; i < 8; i++) {
        acc[i] = (a0[i] + a1[i]) + (a2[i] + a3[i]);
        acc[i] += __shfl_xor_sync(0xffffffffu, acc[i], 8);
        acc[i] += __shfl_xor_sync(0xffffffffu, acc[i], 16);
    }

    if (quarter == 0) {
        float rdeg = 1.0f / fmaxf((float)cnt, 1.0f);
        const float4* S = reinterpret_cast<const float4*>(g_C2s);
        const float4* B = reinterpret_cast<const float4*>(b2);
        float4 s0 = S[node * 16 + 2 * sub];
        float4 s1 = S[node * 16 + 2 * sub + 1];
        float4 bb0 = B[2 * sub];
        float4 bb1 = B[2 * sub + 1];
        float4 o0, o1;
        o0.x = fmaf(acc[0], rdeg, s0.x) + bb0.x;
        o0.y = fmaf(acc[1], rdeg, s0.y) + bb0.y;
        o0.z = fmaf(acc[2], rdeg, s0.z) + bb0.z;
        o0.w = fmaf(acc[3], rdeg, s0.w) + bb0.w;
        o1.x = fmaf(acc[4], rdeg, s1.x) + bb1.x;
        o1.y = fmaf(acc[5], rdeg, s1.y) + bb1.y;
        o1.z = fmaf(acc[6], rdeg, s1.z) + bb1.z;
        o1.w = fmaf(acc[7], rdeg, s1.w) + bb1.w;
        out[node * 16 + 2 * sub] = o0;
        out[node * 16 + 2 * sub + 1] = o1;
    }
}

// ---------------------------------------------------------------------------
// Launch. CSR build forked onto a side stream, overlapped with GEMM1.
// ---------------------------------------------------------------------------
extern "C" void kernel_launch(void* const* d_in, const int* in_sizes, int n_in,
                              void* d_out, int out_size) {
    const float* x   = (const float*)d_in[0];
    const float* Ws1 = (const float*)d_in[1];
    const float* Wn1 = (const float*)d_in[2];
    const float* b1  = (const float*)d_in[3];
    const float* Ws2 = (const float*)d_in[4];
    const float* Wn2 = (const float*)d_in[5];
    const float* b2  = (const float*)d_in[6];
    const int*   src = (const int*)d_in[7];
    const int*   dst = (const int*)d_in[8];
    float4* out = (float4*)d_out;

    float *c1s = nullptr, *c2s = nullptr, *h1 = nullptr;
    __half *p1 = nullptr, *p2 = nullptr;
    cudaGetSymbolAddress((void**)&c1s, g_C1s);
    cudaGetSymbolAddress((void**)&p1,  g_P1);
    cudaGetSymbolAddress((void**)&h1,  g_H1);
    cudaGetSymbolAddress((void**)&c2s, g_C2s);
    cudaGetSymbolAddress((void**)&p2,  g_P2);

    static cudaStream_t s_side = nullptr;
    static cudaEvent_t  s_fork = nullptr, s_join = nullptr;
    if (s_side == nullptr) {
        cudaStreamCreateWithFlags(&s_side, cudaStreamNonBlocking);
        cudaEventCreateWithFlags(&s_fork, cudaEventDisableTiming);
        cudaEventCreateWithFlags(&s_join, cudaEventDisableTiming);
    }

    const int SCAN_BLOCKS = (NNODES + 511) / 512;            // 98
    const int GTILES = (NNODES + 127) / 128;                 // 391
    const int GSMEM = 4 * 128 * 136 * 2;                     // 139264 bytes
    const int AGG_BLOCKS = (NNODES * 32 + 255) / 256;        // warp per node

    cudaFuncSetAttribute((const void*)gemm_mma_kernel<256, 128>,
                         cudaFuncAttributeMaxDynamicSharedMemorySize, GSMEM);
    cudaFuncSetAttribute((const void*)gemm_mma_kernel<128, 64>,
                         cudaFuncAttributeMaxDynamicSharedMemorySize, GSMEM);

    // ---- Fork: CSR build on side stream ----
    cudaEventRecord(s_fork, 0);
    cudaStreamWaitEvent(s_side, s_fork, 0);
    zero_cnt_kernel<<<(NNODES + 255) / 256, 256, 0, s_side>>>();
    hist_kernel<<<(NEDGES + 255) / 256, 256, 0, s_side>>>(dst);
    scanA_kernel<<<SCAN_BLOCKS, 512, 0, s_side>>>();
    scanC_kernel<<<(NNODES + 255) / 256, 256, 0, s_side>>>(SCAN_BLOCKS);
    scatter_kernel<<<(NEDGES + 255) / 256, 256, 0, s_side>>>(src, dst);
    cudaEventRecord(s_join, s_side);

    // ---- Main stream: GEMM1 (weights split in-kernel; independent of CSR) ----
    gemm_mma_kernel<256, 128><<<GTILES, 256, GSMEM>>>(x, Ws1, Wn1, c1s, p1, NNODES);

    // ---- Join: aggregation needs CSR ----
    cudaStreamWaitEvent(0, s_join, 0);
    agg_fin1_kernel<<<AGG_BLOCKS, 256>>>(b1);

    gemm_mma_kernel<128, 64><<<GTILES, 256, GSMEM>>>(h1, Ws2, Wn2, c2s, p2, NNODES);
    agg_fin2_kernel<<<AGG_BLOCKS, 256>>>(b2, out);
}